// round 1
// baseline (speedup 1.0000x reference)
#include <cuda_runtime.h>
#include <cuda_bf16.h>
#include <math.h>

// ---------------- problem constants ----------------
#define B_    128
#define T_    64
#define V_    10000
#define NI_   512
#define ENH   640     // ENC_NH
#define DNH   1024    // DEC_NH
#define NZ_   128
#define ND_   8
#define K_    1024
#define D_    160

#define LOGITS_ELEMS (B_ * T_ * V_)   // 81,920,000

// ---------------- scratch (device globals; allocation-free) ----------------
__device__ __align__(256) float g_we   [B_ * T_ * NI_];         // enc embeddings
__device__ __align__(256) float g_xgf  [B_ * T_ * 4 * ENH];     // fwd input gates
__device__ __align__(256) float g_xgb  [B_ * T_ * 4 * ENH];     // bwd input gates (un-flipped)
__device__ __align__(256) float g_encst[4 * B_ * ENH];          // hf, cf, hb, cb
__device__ __align__(256) float g_gf   [B_ * 4 * ENH];
__device__ __align__(256) float g_gb   [B_ * 4 * ENH];
__device__ __align__(256) float g_fhs  [B_ * 2 * ENH];
__device__ __align__(256) float g_muvar[B_ * 2 * NZ_];
__device__ __align__(256) float g_root [B_ * DNH];
__device__ __align__(256) int   g_inds [B_ * ND_];
__device__ __align__(256) float g_q    [B_ * ND_ * D_];
__device__ __align__(256) float g_vqp  [B_ * ND_];
__device__ __align__(256) float g_suffix[B_ * NI_];
__device__ __align__(256) float g_demb [B_ * T_ * NI_];
__device__ __align__(256) float g_xgd  [B_ * T_ * 4 * DNH];
__device__ __align__(256) float g_hd0  [B_ * DNH];
__device__ __align__(256) float g_cd   [B_ * DNH];
__device__ __align__(256) float g_gd   [B_ * 4 * DNH];
__device__ __align__(256) float g_decout[B_ * T_ * DNH];

// ---------------- generic SGEMM: C[m,n] = sum_k A[m,k]*W[n,k] (+bias[n]) (+Cadd[m,n]) ----------------
// Assumes M % BM == 0, K % BK == 0, K % 4 == 0, lda/ldw % 4 == 0. N arbitrary (guarded).
template<int BM, int BN, int BK, int TM, int TN>
__global__ __launch_bounds__((BM/TM)*(BN/TN))
void gemm_k(const float* __restrict__ A, int lda,
            const float* __restrict__ W, int ldw,
            const float* __restrict__ bias,
            const float* __restrict__ Cadd, int ldca,
            float* __restrict__ C, int ldc,
            int N, int K)
{
    constexpr int NT = (BM/TM)*(BN/TN);
    __shared__ __align__(16) float As[BK][BM + 4];
    __shared__ __align__(16) float Ws[BK][BN + 4];

    const int tid  = threadIdx.x;
    const int row0 = blockIdx.y * BM;
    const int col0 = blockIdx.x * BN;
    const int tr   = tid / (BN / TN);
    const int tc   = tid % (BN / TN);

    float acc[TM][TN];
#pragma unroll
    for (int i = 0; i < TM; i++)
#pragma unroll
        for (int j = 0; j < TN; j++) acc[i][j] = 0.f;

    for (int k0 = 0; k0 < K; k0 += BK) {
        // load A tile (BM x BK), stored transposed As[k][m]
#pragma unroll
        for (int idx = tid * 4; idx < BM * BK; idx += NT * 4) {
            int m  = idx / BK;
            int kk = idx % BK;
            float4 v = *reinterpret_cast<const float4*>(A + (size_t)(row0 + m) * lda + (k0 + kk));
            As[kk + 0][m] = v.x; As[kk + 1][m] = v.y; As[kk + 2][m] = v.z; As[kk + 3][m] = v.w;
        }
        // load W tile (BN x BK), stored transposed Ws[k][n]; rows >= N are zero-filled
#pragma unroll
        for (int idx = tid * 4; idx < BN * BK; idx += NT * 4) {
            int n  = idx / BK;
            int kk = idx % BK;
            float4 v = make_float4(0.f, 0.f, 0.f, 0.f);
            if (col0 + n < N)
                v = *reinterpret_cast<const float4*>(W + (size_t)(col0 + n) * ldw + (k0 + kk));
            Ws[kk + 0][n] = v.x; Ws[kk + 1][n] = v.y; Ws[kk + 2][n] = v.z; Ws[kk + 3][n] = v.w;
        }
        __syncthreads();

#pragma unroll
        for (int kk = 0; kk < BK; kk++) {
            float ra[TM], rb[TN];
#pragma unroll
            for (int i = 0; i < TM; i += 4) {
                float4 v = *reinterpret_cast<const float4*>(&As[kk][tr * TM + i]);
                ra[i] = v.x; ra[i+1] = v.y; ra[i+2] = v.z; ra[i+3] = v.w;
            }
#pragma unroll
            for (int j = 0; j < TN; j += 4) {
                float4 v = *reinterpret_cast<const float4*>(&Ws[kk][tc * TN + j]);
                rb[j] = v.x; rb[j+1] = v.y; rb[j+2] = v.z; rb[j+3] = v.w;
            }
#pragma unroll
            for (int i = 0; i < TM; i++)
#pragma unroll
                for (int j = 0; j < TN; j++)
                    acc[i][j] = fmaf(ra[i], rb[j], acc[i][j]);
        }
        __syncthreads();
    }

#pragma unroll
    for (int i = 0; i < TM; i++) {
        int m = row0 + tr * TM + i;
#pragma unroll
        for (int j = 0; j < TN; j++) {
            int n = col0 + tc * TN + j;
            if (n < N) {
                float v = acc[i][j];
                if (bias) v += bias[n];
                if (Cadd) v += Cadd[(size_t)m * ldca + n];
                C[(size_t)m * ldc + n] = v;
            }
        }
    }
}

// ---------------- elementwise / small kernels ----------------
__device__ __forceinline__ float sigf(float x) { return 1.f / (1.f + expf(-x)); }

__global__ void embed_kernel(const int* __restrict__ x, const float* __restrict__ emb,
                             float* __restrict__ out)
{
    size_t idx = (size_t)blockIdx.x * blockDim.x + threadIdx.x;
    if (idx >= (size_t)B_ * T_ * NI_) return;
    int i  = (int)(idx % NI_);
    int bt = (int)(idx / NI_);
    int tok = x[bt];
    out[idx] = emb[(size_t)tok * NI_ + i];
}

__global__ void demb_kernel(const int* __restrict__ x, const float* __restrict__ emb,
                            const float* __restrict__ suffix, float* __restrict__ out)
{
    size_t idx = (size_t)blockIdx.x * blockDim.x + threadIdx.x;
    if (idx >= (size_t)B_ * T_ * NI_) return;
    int i  = (int)(idx % NI_);
    int bt = (int)(idx / NI_);
    int b  = bt / T_;
    int tok = x[bt];
    out[idx] = emb[(size_t)tok * NI_ + i] + suffix[(size_t)b * NI_ + i];
}

__global__ void enc_gates(const float* __restrict__ gf, const float* __restrict__ gb,
                          float* __restrict__ hf, float* __restrict__ cf,
                          float* __restrict__ hb, float* __restrict__ cb)
{
    int idx = blockIdx.x * blockDim.x + threadIdx.x;
    const int n = B_ * ENH;
    if (idx >= 2 * n) return;
    const float* g; float* h; float* c; int j2 = idx;
    if (idx < n) { g = gf; h = hf; c = cf; }
    else         { g = gb; h = hb; c = cb; j2 = idx - n; }
    int b = j2 / ENH, j = j2 % ENH;
    const float* gr = g + (size_t)b * 4 * ENH;
    float iv = sigf(gr[j]);
    float fv = sigf(gr[ENH + j]);
    float gv = tanhf(gr[2 * ENH + j]);
    float ov = sigf(gr[3 * ENH + j]);
    float cc = fv * c[j2] + iv * gv;
    c[j2] = cc;
    h[j2] = ov * tanhf(cc);
}

__global__ void dec_gates(const float* __restrict__ g, float* __restrict__ c,
                          float* __restrict__ hout /* decout + s*DNH, row stride T_*DNH */)
{
    int idx = blockIdx.x * blockDim.x + threadIdx.x;
    if (idx >= B_ * DNH) return;
    int b = idx / DNH, j = idx % DNH;
    const float* gr = g + (size_t)b * 4 * DNH;
    float iv = sigf(gr[j]);
    float fv = sigf(gr[DNH + j]);
    float gv = tanhf(gr[2 * DNH + j]);
    float ov = sigf(gr[3 * DNH + j]);
    float cc = fv * c[idx] + iv * gv;
    c[idx] = cc;
    hout[(size_t)b * (T_ * DNH) + j] = ov * tanhf(cc);
}

__global__ void concat_fhs(const float* __restrict__ hf, const float* __restrict__ hb,
                           float* __restrict__ fhs)
{
    int idx = blockIdx.x * blockDim.x + threadIdx.x;
    if (idx >= B_ * 2 * ENH) return;
    int b = idx / (2 * ENH), j = idx % (2 * ENH);
    fhs[idx] = (j < ENH) ? hf[(size_t)b * ENH + j] : hb[(size_t)b * ENH + (j - ENH)];
}

__global__ void kl_kernel(const float* __restrict__ muvar, float* __restrict__ out_kl)
{
    int b = threadIdx.x;
    if (b >= B_) return;
    float s = 0.f;
    const float* row = muvar + (size_t)b * 2 * NZ_;
    for (int j = 0; j < NZ_; j++) {
        float mu = row[j], lv = row[NZ_ + j];
        s += mu * mu + expf(lv) - lv - 1.f;
    }
    out_kl[b] = 0.5f * s;
}

__global__ void dec_init(const float* __restrict__ root, float* __restrict__ h0,
                         float* __restrict__ c0)
{
    int idx = blockIdx.x * blockDim.x + threadIdx.x;
    if (idx >= B_ * DNH) return;
    float r = root[idx];
    h0[idx] = tanhf(r);
    c0[idx] = r;
}

// one block per (b, n): argmin over K_ codes (sum(cb^2) - 2*lat.cb ; sum(lat^2) is constant),
// then gather q (with straight-through rounding lat + (q - lat)) and mean squared diff.
__global__ void vq_kernel(const float* __restrict__ fhs, const float* __restrict__ cb,
                          int* __restrict__ inds, float* __restrict__ q,
                          float* __restrict__ vqp)
{
    const int bn = blockIdx.x;
    const int b = bn / ND_, n = bn % ND_;
    __shared__ __align__(16) float lat[D_];
    __shared__ float svals[256];
    __shared__ int   sidx[256];
    const float* latg = fhs + (size_t)b * (ND_ * D_) + (size_t)n * D_;
    for (int d = threadIdx.x; d < D_; d += 256) lat[d] = latg[d];
    __syncthreads();

    float best = INFINITY; int bidx = K_;
    const float* cbn = cb + (size_t)n * K_ * D_;
    for (int k = threadIdx.x; k < K_; k += 256) {
        const float4* ck = reinterpret_cast<const float4*>(cbn + (size_t)k * D_);
        float t1 = 0.f, t2 = 0.f;
#pragma unroll
        for (int d4 = 0; d4 < D_ / 4; d4++) {
            float4 cv = ck[d4];
            const float4 lv = *reinterpret_cast<const float4*>(&lat[d4 * 4]);
            t1 = fmaf(cv.x, cv.x, t1); t2 = fmaf(cv.x, lv.x, t2);
            t1 = fmaf(cv.y, cv.y, t1); t2 = fmaf(cv.y, lv.y, t2);
            t1 = fmaf(cv.z, cv.z, t1); t2 = fmaf(cv.z, lv.z, t2);
            t1 = fmaf(cv.w, cv.w, t1); t2 = fmaf(cv.w, lv.w, t2);
        }
        float dist = t1 - 2.f * t2;
        if (dist < best || (dist == best && k < bidx)) { best = dist; bidx = k; }
    }
    svals[threadIdx.x] = best; sidx[threadIdx.x] = bidx;
    __syncthreads();
    for (int off = 128; off > 0; off >>= 1) {
        if (threadIdx.x < off) {
            float v = svals[threadIdx.x + off]; int i2 = sidx[threadIdx.x + off];
            if (v < svals[threadIdx.x] ||
                (v == svals[threadIdx.x] && i2 < sidx[threadIdx.x])) {
                svals[threadIdx.x] = v; sidx[threadIdx.x] = i2;
            }
        }
        __syncthreads();
    }
    const int kmin = sidx[0];
    if (threadIdx.x == 0) inds[bn] = kmin;
    __syncthreads();

    const float* ck = cbn + (size_t)kmin * D_;
    float part = 0.f;
    for (int d = threadIdx.x; d < D_; d += 256) {
        float qv = ck[d], lv = lat[d];
        float diff = qv - lv;
        q[(size_t)bn * D_ + d] = lv + diff;   // straight-through forward value
        part += diff * diff;
    }
    svals[threadIdx.x] = part;
    __syncthreads();
    for (int off = 128; off > 0; off >>= 1) {
        if (threadIdx.x < off) svals[threadIdx.x] += svals[threadIdx.x + off];
        __syncthreads();
    }
    if (threadIdx.x == 0) vqp[bn] = svals[0] / (float)D_;
}

__global__ void vq_finish(const float* __restrict__ vqp, const int* __restrict__ inds,
                          float* __restrict__ out_vq, float* __restrict__ out_inds)
{
    int b = threadIdx.x;
    if (b >= B_) return;
    float s = 0.f;
#pragma unroll
    for (int n = 0; n < ND_; n++) s += vqp[b * ND_ + n];
    out_vq[b] = 1.25f * s;   // embl + BETA*commit, numerically equal terms
#pragma unroll
    for (int n = 0; n < ND_; n++)
        out_inds[b * ND_ + n] = (float)inds[b * ND_ + n];
}

// ---------------- host-side launch helpers ----------------
static inline void gemm_big(const float* A, int lda, const float* W, int ldw,
                            const float* bias, const float* Cadd, int ldca,
                            float* C, int ldc, int M, int N, int K)
{
    dim3 grid((N + 127) / 128, M / 128);
    gemm_k<128, 128, 16, 8, 8><<<grid, 256>>>(A, lda, W, ldw, bias, Cadd, ldca, C, ldc, N, K);
}

static inline void gemm_small(const float* A, int lda, const float* W, int ldw,
                              const float* bias, const float* Cadd, int ldca,
                              float* C, int ldc, int M, int N, int K)
{
    dim3 grid((N + 63) / 64, M / 32);
    gemm_k<32, 64, 16, 4, 4><<<grid, 128>>>(A, lda, W, ldw, bias, Cadd, ldca, C, ldc, N, K);
}

extern "C" void kernel_launch(void* const* d_in, const int* in_sizes, int n_in,
                              void* d_out, int out_size)
{
    (void)in_sizes; (void)n_in; (void)out_size;
    const int*   x         = (const int*)  d_in[0];
    const float* enc_embed = (const float*)d_in[1];
    const float* enc_Wih_f = (const float*)d_in[2];
    const float* enc_Whh_f = (const float*)d_in[3];
    const float* enc_b_f   = (const float*)d_in[4];
    const float* enc_Wih_b = (const float*)d_in[5];
    const float* enc_Whh_b = (const float*)d_in[6];
    const float* enc_b_b   = (const float*)d_in[7];
    const float* enc_lin   = (const float*)d_in[8];
    const float* z2dec_W   = (const float*)d_in[9];
    const float* z2dec_b   = (const float*)d_in[10];
    const float* codebooks = (const float*)d_in[11];
    const float* suffix_W  = (const float*)d_in[12];
    const float* dec_embed = (const float*)d_in[13];
    const float* dec_Wih   = (const float*)d_in[14];
    const float* dec_Whh   = (const float*)d_in[15];
    const float* dec_b     = (const float*)d_in[16];
    const float* pred_W    = (const float*)d_in[17];

    float* out       = (float*)d_out;
    float* out_log   = out;
    float* out_vq    = out + (size_t)LOGITS_ELEMS;
    float* out_kl    = out_vq + B_;
    float* out_inds  = out_kl + B_;

    float *we, *xgf, *xgb, *encst, *gf, *gb, *fhs, *muvar, *root, *q, *vqp, *suffix;
    float *demb, *xgd, *hd0, *cd, *gd, *decout;
    int* inds;
    cudaGetSymbolAddress((void**)&we,    g_we);
    cudaGetSymbolAddress((void**)&xgf,   g_xgf);
    cudaGetSymbolAddress((void**)&xgb,   g_xgb);
    cudaGetSymbolAddress((void**)&encst, g_encst);
    cudaGetSymbolAddress((void**)&gf,    g_gf);
    cudaGetSymbolAddress((void**)&gb,    g_gb);
    cudaGetSymbolAddress((void**)&fhs,   g_fhs);
    cudaGetSymbolAddress((void**)&muvar, g_muvar);
    cudaGetSymbolAddress((void**)&root,  g_root);
    cudaGetSymbolAddress((void**)&inds,  g_inds);
    cudaGetSymbolAddress((void**)&q,     g_q);
    cudaGetSymbolAddress((void**)&vqp,   g_vqp);
    cudaGetSymbolAddress((void**)&suffix,g_suffix);
    cudaGetSymbolAddress((void**)&demb,  g_demb);
    cudaGetSymbolAddress((void**)&xgd,   g_xgd);
    cudaGetSymbolAddress((void**)&hd0,   g_hd0);
    cudaGetSymbolAddress((void**)&cd,    g_cd);
    cudaGetSymbolAddress((void**)&gd,    g_gd);
    cudaGetSymbolAddress((void**)&decout,g_decout);

    float* hf = encst;
    float* cf = encst + (size_t)B_ * ENH;
    float* hb = encst + (size_t)2 * B_ * ENH;
    float* cb = encst + (size_t)3 * B_ * ENH;

    const int EW = 256;

    // 1) encoder embedding gather
    embed_kernel<<<(B_ * T_ * NI_ + EW - 1) / EW, EW>>>(x, enc_embed, we);

    // 2) input-gate GEMMs (bias fused). xgb is computed un-flipped; LSTM reads reversed slices.
    gemm_big(we, NI_, enc_Wih_f, NI_, enc_b_f, nullptr, 0, xgf, 4 * ENH, B_ * T_, 4 * ENH, NI_);
    gemm_big(we, NI_, enc_Wih_b, NI_, enc_b_b, nullptr, 0, xgb, 4 * ENH, B_ * T_, 4 * ENH, NI_);

    // 3) zero encoder h/c state
    cudaMemsetAsync(encst, 0, sizeof(float) * 4 * B_ * ENH, 0);

    // 4) encoder recurrence (fwd + bwd per step)
    for (int s = 0; s < T_; s++) {
        gemm_small(hf, ENH, enc_Whh_f, ENH, nullptr,
                   xgf + (size_t)s * 4 * ENH, T_ * 4 * ENH,
                   gf, 4 * ENH, B_, 4 * ENH, ENH);
        gemm_small(hb, ENH, enc_Whh_b, ENH, nullptr,
                   xgb + (size_t)(T_ - 1 - s) * 4 * ENH, T_ * 4 * ENH,
                   gb, 4 * ENH, B_, 4 * ENH, ENH);
        enc_gates<<<(2 * B_ * ENH + EW - 1) / EW, EW>>>(gf, gb, hf, cf, hb, cb);
    }

    // 5) fhs = [hf, hb]
    concat_fhs<<<(B_ * 2 * ENH + EW - 1) / EW, EW>>>(hf, hb, fhs);

    // 6) mu/logvar
    gemm_small(fhs, 2 * ENH, enc_lin, 2 * ENH, nullptr, nullptr, 0,
               muvar, 2 * NZ_, B_, 2 * NZ_, 2 * ENH);

    // 7) kl
    kl_kernel<<<1, B_>>>(muvar, out_kl);

    // 8) root = mu @ z2dec_W^T + b   (mu = muvar[:, :NZ_], lda = 2*NZ_)
    gemm_small(muvar, 2 * NZ_, z2dec_W, NZ_, z2dec_b, nullptr, 0,
               root, DNH, B_, DNH, NZ_);

    // 9) VQ
    vq_kernel<<<B_ * ND_, 256>>>(fhs, codebooks, inds, q, vqp);
    vq_finish<<<1, B_>>>(vqp, inds, out_vq, out_inds);

    // 10) suffix = q_st @ suffix_W^T
    gemm_small(q, ND_ * D_, suffix_W, ND_ * D_, nullptr, nullptr, 0,
               suffix, NI_, B_, NI_, ND_ * D_);

    // 11) decoder embeddings + suffix broadcast
    demb_kernel<<<(B_ * T_ * NI_ + EW - 1) / EW, EW>>>(x, dec_embed, suffix, demb);

    // 12) decoder input gates
    gemm_big(demb, NI_, dec_Wih, NI_, dec_b, nullptr, 0, xgd, 4 * DNH, B_ * T_, 4 * DNH, NI_);

    // 13) decoder init: h0 = tanh(root), c0 = root
    dec_init<<<(B_ * DNH + EW - 1) / EW, EW>>>(root, hd0, cd);

    // 14) decoder recurrence; h written straight into decout slices
    for (int s = 0; s < T_; s++) {
        const float* A   = (s == 0) ? hd0 : (decout + (size_t)(s - 1) * DNH);
        int          lda = (s == 0) ? DNH : (T_ * DNH);
        gemm_small(A, lda, dec_Whh, DNH, nullptr,
                   xgd + (size_t)s * 4 * DNH, T_ * 4 * DNH,
                   gd, 4 * DNH, B_, 4 * DNH, DNH);
        dec_gates<<<(B_ * DNH + EW - 1) / EW, EW>>>(gd, cd, decout + (size_t)s * DNH);
    }

    // 15) logits = decout @ pred_W^T  (N = 10000 guarded)
    gemm_big(decout, DNH, pred_W, DNH, nullptr, nullptr, 0,
             out_log, V_, B_ * T_, V_, DNH);
}

// round 2
// speedup vs baseline: 1.0019x; 1.0019x over previous
#include <cuda_runtime.h>
#include <cuda_bf16.h>
#include <math.h>

// ---------------- problem constants ----------------
#define B_    128
#define T_    64
#define V_    10000
#define NI_   512
#define ENH   640     // ENC_NH
#define DNH   1024    // DEC_NH
#define NZ_   128
#define ND_   8
#define K_    1024
#define D_    160

#define LOGITS_ELEMS (B_ * T_ * V_)   // 81,920,000

// ---------------- scratch (device globals; allocation-free) ----------------
__device__ __align__(256) float g_we   [B_ * T_ * NI_];         // enc embeddings
__device__ __align__(256) float g_xgf  [B_ * T_ * 4 * ENH];     // fwd input gates
__device__ __align__(256) float g_xgb  [B_ * T_ * 4 * ENH];     // bwd input gates (un-flipped)
__device__ __align__(256) float g_encst[4 * B_ * ENH];          // hf, cf, hb, cb
__device__ __align__(256) float g_gf   [B_ * 4 * ENH];
__device__ __align__(256) float g_gb   [B_ * 4 * ENH];
__device__ __align__(256) float g_fhs  [B_ * 2 * ENH];
__device__ __align__(256) float g_muvar[B_ * 2 * NZ_];
__device__ __align__(256) float g_root [B_ * DNH];
__device__ __align__(256) int   g_inds [B_ * ND_];
__device__ __align__(256) float g_q    [B_ * ND_ * D_];
__device__ __align__(256) float g_vqp  [B_ * ND_];
__device__ __align__(256) float g_suffix[B_ * NI_];
__device__ __align__(256) float g_demb [B_ * T_ * NI_];
__device__ __align__(256) float g_xgd  [B_ * T_ * 4 * DNH];
__device__ __align__(256) float g_hd0  [B_ * DNH];
__device__ __align__(256) float g_cd   [B_ * DNH];
__device__ __align__(256) float g_gd   [B_ * 4 * DNH];
__device__ __align__(256) float g_decout[B_ * T_ * DNH];

// ---------------- generic SGEMM: C[m,n] = sum_k A[m,k]*W[n,k] (+bias[n]) (+Cadd[m,n]) ----------------
// Assumes M % BM == 0, K % BK == 0, K % 4 == 0, lda/ldw % 4 == 0. N arbitrary (guarded).
template<int BM, int BN, int BK, int TM, int TN>
__global__ __launch_bounds__((BM/TM)*(BN/TN))
void gemm_k(const float* __restrict__ A, int lda,
            const float* __restrict__ W, int ldw,
            const float* __restrict__ bias,
            const float* __restrict__ Cadd, int ldca,
            float* __restrict__ C, int ldc,
            int N, int K)
{
    constexpr int NT = (BM/TM)*(BN/TN);
    __shared__ __align__(16) float As[BK][BM + 4];
    __shared__ __align__(16) float Ws[BK][BN + 4];

    const int tid  = threadIdx.x;
    const int row0 = blockIdx.y * BM;
    const int col0 = blockIdx.x * BN;
    const int tr   = tid / (BN / TN);
    const int tc   = tid % (BN / TN);

    float acc[TM][TN];
#pragma unroll
    for (int i = 0; i < TM; i++)
#pragma unroll
        for (int j = 0; j < TN; j++) acc[i][j] = 0.f;

    for (int k0 = 0; k0 < K; k0 += BK) {
        // load A tile (BM x BK), stored transposed As[k][m]
#pragma unroll
        for (int idx = tid * 4; idx < BM * BK; idx += NT * 4) {
            int m  = idx / BK;
            int kk = idx % BK;
            float4 v = *reinterpret_cast<const float4*>(A + (size_t)(row0 + m) * lda + (k0 + kk));
            As[kk + 0][m] = v.x; As[kk + 1][m] = v.y; As[kk + 2][m] = v.z; As[kk + 3][m] = v.w;
        }
        // load W tile (BN x BK), stored transposed Ws[k][n]; rows >= N are zero-filled
#pragma unroll
        for (int idx = tid * 4; idx < BN * BK; idx += NT * 4) {
            int n  = idx / BK;
            int kk = idx % BK;
            float4 v = make_float4(0.f, 0.f, 0.f, 0.f);
            if (col0 + n < N)
                v = *reinterpret_cast<const float4*>(W + (size_t)(col0 + n) * ldw + (k0 + kk));
            Ws[kk + 0][n] = v.x; Ws[kk + 1][n] = v.y; Ws[kk + 2][n] = v.z; Ws[kk + 3][n] = v.w;
        }
        __syncthreads();

#pragma unroll
        for (int kk = 0; kk < BK; kk++) {
            float ra[TM], rb[TN];
#pragma unroll
            for (int i = 0; i < TM; i += 4) {
                float4 v = *reinterpret_cast<const float4*>(&As[kk][tr * TM + i]);
                ra[i] = v.x; ra[i+1] = v.y; ra[i+2] = v.z; ra[i+3] = v.w;
            }
#pragma unroll
            for (int j = 0; j < TN; j += 4) {
                float4 v = *reinterpret_cast<const float4*>(&Ws[kk][tc * TN + j]);
                rb[j] = v.x; rb[j+1] = v.y; rb[j+2] = v.z; rb[j+3] = v.w;
            }
#pragma unroll
            for (int i = 0; i < TM; i++)
#pragma unroll
                for (int j = 0; j < TN; j++)
                    acc[i][j] = fmaf(ra[i], rb[j], acc[i][j]);
        }
        __syncthreads();
    }

#pragma unroll
    for (int i = 0; i < TM; i++) {
        int m = row0 + tr * TM + i;
#pragma unroll
        for (int j = 0; j < TN; j++) {
            int n = col0 + tc * TN + j;
            if (n < N) {
                float v = acc[i][j];
                if (bias) v += bias[n];
                if (Cadd) v += Cadd[(size_t)m * ldca + n];
                C[(size_t)m * ldc + n] = v;
            }
        }
    }
}

// ---------------- elementwise / small kernels ----------------
__device__ __forceinline__ float sigf(float x) { return 1.f / (1.f + expf(-x)); }

__global__ void embed_kernel(const int* __restrict__ x, const float* __restrict__ emb,
                             float* __restrict__ out)
{
    size_t idx = (size_t)blockIdx.x * blockDim.x + threadIdx.x;
    if (idx >= (size_t)B_ * T_ * NI_) return;
    int i  = (int)(idx % NI_);
    int bt = (int)(idx / NI_);
    int tok = x[bt];
    out[idx] = emb[(size_t)tok * NI_ + i];
}

__global__ void demb_kernel(const int* __restrict__ x, const float* __restrict__ emb,
                            const float* __restrict__ suffix, float* __restrict__ out)
{
    size_t idx = (size_t)blockIdx.x * blockDim.x + threadIdx.x;
    if (idx >= (size_t)B_ * T_ * NI_) return;
    int i  = (int)(idx % NI_);
    int bt = (int)(idx / NI_);
    int b  = bt / T_;
    int tok = x[bt];
    out[idx] = emb[(size_t)tok * NI_ + i] + suffix[(size_t)b * NI_ + i];
}

__global__ void enc_gates(const float* __restrict__ gf, const float* __restrict__ gb,
                          float* __restrict__ hf, float* __restrict__ cf,
                          float* __restrict__ hb, float* __restrict__ cb)
{
    int idx = blockIdx.x * blockDim.x + threadIdx.x;
    const int n = B_ * ENH;
    if (idx >= 2 * n) return;
    const float* g; float* h; float* c; int j2 = idx;
    if (idx < n) { g = gf; h = hf; c = cf; }
    else         { g = gb; h = hb; c = cb; j2 = idx - n; }
    int b = j2 / ENH, j = j2 % ENH;
    const float* gr = g + (size_t)b * 4 * ENH;
    float iv = sigf(gr[j]);
    float fv = sigf(gr[ENH + j]);
    float gv = tanhf(gr[2 * ENH + j]);
    float ov = sigf(gr[3 * ENH + j]);
    float cc = fv * c[j2] + iv * gv;
    c[j2] = cc;
    h[j2] = ov * tanhf(cc);
}

__global__ void dec_gates(const float* __restrict__ g, float* __restrict__ c,
                          float* __restrict__ hout /* decout + s*DNH, row stride T_*DNH */)
{
    int idx = blockIdx.x * blockDim.x + threadIdx.x;
    if (idx >= B_ * DNH) return;
    int b = idx / DNH, j = idx % DNH;
    const float* gr = g + (size_t)b * 4 * DNH;
    float iv = sigf(gr[j]);
    float fv = sigf(gr[DNH + j]);
    float gv = tanhf(gr[2 * DNH + j]);
    float ov = sigf(gr[3 * DNH + j]);
    float cc = fv * c[idx] + iv * gv;
    c[idx] = cc;
    hout[(size_t)b * (T_ * DNH) + j] = ov * tanhf(cc);
}

__global__ void concat_fhs(const float* __restrict__ hf, const float* __restrict__ hb,
                           float* __restrict__ fhs)
{
    int idx = blockIdx.x * blockDim.x + threadIdx.x;
    if (idx >= B_ * 2 * ENH) return;
    int b = idx / (2 * ENH), j = idx % (2 * ENH);
    fhs[idx] = (j < ENH) ? hf[(size_t)b * ENH + j] : hb[(size_t)b * ENH + (j - ENH)];
}

__global__ void kl_kernel(const float* __restrict__ muvar, float* __restrict__ out_kl)
{
    int b = threadIdx.x;
    if (b >= B_) return;
    float s = 0.f;
    const float* row = muvar + (size_t)b * 2 * NZ_;
    for (int j = 0; j < NZ_; j++) {
        float mu = row[j], lv = row[NZ_ + j];
        s += mu * mu + expf(lv) - lv - 1.f;
    }
    out_kl[b] = 0.5f * s;
}

__global__ void dec_init(const float* __restrict__ root, float* __restrict__ h0,
                         float* __restrict__ c0)
{
    int idx = blockIdx.x * blockDim.x + threadIdx.x;
    if (idx >= B_ * DNH) return;
    float r = root[idx];
    h0[idx] = tanhf(r);
    c0[idx] = r;
}

// one block per (b, n): argmin over K_ codes (sum(cb^2) - 2*lat.cb ; sum(lat^2) is constant),
// then gather q (with straight-through rounding lat + (q - lat)) and mean squared diff.
__global__ void vq_kernel(const float* __restrict__ fhs, const float* __restrict__ cb,
                          int* __restrict__ inds, float* __restrict__ q,
                          float* __restrict__ vqp)
{
    const int bn = blockIdx.x;
    const int b = bn / ND_, n = bn % ND_;
    __shared__ __align__(16) float lat[D_];
    __shared__ float svals[256];
    __shared__ int   sidx[256];
    const float* latg = fhs + (size_t)b * (ND_ * D_) + (size_t)n * D_;
    for (int d = threadIdx.x; d < D_; d += 256) lat[d] = latg[d];
    __syncthreads();

    float best = INFINITY; int bidx = K_;
    const float* cbn = cb + (size_t)n * K_ * D_;
    for (int k = threadIdx.x; k < K_; k += 256) {
        const float4* ck = reinterpret_cast<const float4*>(cbn + (size_t)k * D_);
        float t1 = 0.f, t2 = 0.f;
#pragma unroll
        for (int d4 = 0; d4 < D_ / 4; d4++) {
            float4 cv = ck[d4];
            const float4 lv = *reinterpret_cast<const float4*>(&lat[d4 * 4]);
            t1 = fmaf(cv.x, cv.x, t1); t2 = fmaf(cv.x, lv.x, t2);
            t1 = fmaf(cv.y, cv.y, t1); t2 = fmaf(cv.y, lv.y, t2);
            t1 = fmaf(cv.z, cv.z, t1); t2 = fmaf(cv.z, lv.z, t2);
            t1 = fmaf(cv.w, cv.w, t1); t2 = fmaf(cv.w, lv.w, t2);
        }
        float dist = t1 - 2.f * t2;
        if (dist < best || (dist == best && k < bidx)) { best = dist; bidx = k; }
    }
    svals[threadIdx.x] = best; sidx[threadIdx.x] = bidx;
    __syncthreads();
    for (int off = 128; off > 0; off >>= 1) {
        if (threadIdx.x < off) {
            float v = svals[threadIdx.x + off]; int i2 = sidx[threadIdx.x + off];
            if (v < svals[threadIdx.x] ||
                (v == svals[threadIdx.x] && i2 < sidx[threadIdx.x])) {
                svals[threadIdx.x] = v; sidx[threadIdx.x] = i2;
            }
        }
        __syncthreads();
    }
    const int kmin = sidx[0];
    if (threadIdx.x == 0) inds[bn] = kmin;
    __syncthreads();

    const float* ck = cbn + (size_t)kmin * D_;
    float part = 0.f;
    for (int d = threadIdx.x; d < D_; d += 256) {
        float qv = ck[d], lv = lat[d];
        float diff = qv - lv;
        q[(size_t)bn * D_ + d] = lv + diff;   // straight-through forward value
        part += diff * diff;
    }
    svals[threadIdx.x] = part;
    __syncthreads();
    for (int off = 128; off > 0; off >>= 1) {
        if (threadIdx.x < off) svals[threadIdx.x] += svals[threadIdx.x + off];
        __syncthreads();
    }
    if (threadIdx.x == 0) vqp[bn] = svals[0] / (float)D_;
}

__global__ void vq_finish(const float* __restrict__ vqp, const int* __restrict__ inds,
                          float* __restrict__ out_vq, float* __restrict__ out_inds)
{
    int b = threadIdx.x;
    if (b >= B_) return;
    float s = 0.f;
#pragma unroll
    for (int n = 0; n < ND_; n++) s += vqp[b * ND_ + n];
    out_vq[b] = 1.25f * s;   // embl + BETA*commit, numerically equal terms
#pragma unroll
    for (int n = 0; n < ND_; n++)
        out_inds[b * ND_ + n] = (float)inds[b * ND_ + n];
}

// ---------------- host-side launch helpers ----------------
static inline void gemm_big(const float* A, int lda, const float* W, int ldw,
                            const float* bias, const float* Cadd, int ldca,
                            float* C, int ldc, int M, int N, int K)
{
    dim3 grid((N + 127) / 128, M / 128);
    gemm_k<128, 128, 16, 8, 8><<<grid, 256>>>(A, lda, W, ldw, bias, Cadd, ldca, C, ldc, N, K);
}

static inline void gemm_small(const float* A, int lda, const float* W, int ldw,
                              const float* bias, const float* Cadd, int ldca,
                              float* C, int ldc, int M, int N, int K)
{
    dim3 grid((N + 63) / 64, M / 32);
    gemm_k<32, 64, 16, 4, 4><<<grid, 128>>>(A, lda, W, ldw, bias, Cadd, ldca, C, ldc, N, K);
}

extern "C" void kernel_launch(void* const* d_in, const int* in_sizes, int n_in,
                              void* d_out, int out_size)
{
    (void)in_sizes; (void)n_in; (void)out_size;
    const int*   x         = (const int*)  d_in[0];
    const float* enc_embed = (const float*)d_in[1];
    const float* enc_Wih_f = (const float*)d_in[2];
    const float* enc_Whh_f = (const float*)d_in[3];
    const float* enc_b_f   = (const float*)d_in[4];
    const float* enc_Wih_b = (const float*)d_in[5];
    const float* enc_Whh_b = (const float*)d_in[6];
    const float* enc_b_b   = (const float*)d_in[7];
    const float* enc_lin   = (const float*)d_in[8];
    const float* z2dec_W   = (const float*)d_in[9];
    const float* z2dec_b   = (const float*)d_in[10];
    const float* codebooks = (const float*)d_in[11];
    const float* suffix_W  = (const float*)d_in[12];
    const float* dec_embed = (const float*)d_in[13];
    const float* dec_Wih   = (const float*)d_in[14];
    const float* dec_Whh   = (const float*)d_in[15];
    const float* dec_b     = (const float*)d_in[16];
    const float* pred_W    = (const float*)d_in[17];

    float* out       = (float*)d_out;
    float* out_log   = out;
    float* out_vq    = out + (size_t)LOGITS_ELEMS;
    float* out_kl    = out_vq + B_;
    float* out_inds  = out_kl + B_;

    float *we, *xgf, *xgb, *encst, *gf, *gb, *fhs, *muvar, *root, *q, *vqp, *suffix;
    float *demb, *xgd, *hd0, *cd, *gd, *decout;
    int* inds;
    cudaGetSymbolAddress((void**)&we,    g_we);
    cudaGetSymbolAddress((void**)&xgf,   g_xgf);
    cudaGetSymbolAddress((void**)&xgb,   g_xgb);
    cudaGetSymbolAddress((void**)&encst, g_encst);
    cudaGetSymbolAddress((void**)&gf,    g_gf);
    cudaGetSymbolAddress((void**)&gb,    g_gb);
    cudaGetSymbolAddress((void**)&fhs,   g_fhs);
    cudaGetSymbolAddress((void**)&muvar, g_muvar);
    cudaGetSymbolAddress((void**)&root,  g_root);
    cudaGetSymbolAddress((void**)&inds,  g_inds);
    cudaGetSymbolAddress((void**)&q,     g_q);
    cudaGetSymbolAddress((void**)&vqp,   g_vqp);
    cudaGetSymbolAddress((void**)&suffix,g_suffix);
    cudaGetSymbolAddress((void**)&demb,  g_demb);
    cudaGetSymbolAddress((void**)&xgd,   g_xgd);
    cudaGetSymbolAddress((void**)&hd0,   g_hd0);
    cudaGetSymbolAddress((void**)&cd,    g_cd);
    cudaGetSymbolAddress((void**)&gd,    g_gd);
    cudaGetSymbolAddress((void**)&decout,g_decout);

    float* hf = encst;
    float* cf = encst + (size_t)B_ * ENH;
    float* hb = encst + (size_t)2 * B_ * ENH;
    float* cb = encst + (size_t)3 * B_ * ENH;

    const int EW = 256;

    // 1) encoder embedding gather
    embed_kernel<<<(B_ * T_ * NI_ + EW - 1) / EW, EW>>>(x, enc_embed, we);

    // 2) input-gate GEMMs (bias fused). xgb is computed un-flipped; LSTM reads reversed slices.
    gemm_big(we, NI_, enc_Wih_f, NI_, enc_b_f, nullptr, 0, xgf, 4 * ENH, B_ * T_, 4 * ENH, NI_);
    gemm_big(we, NI_, enc_Wih_b, NI_, enc_b_b, nullptr, 0, xgb, 4 * ENH, B_ * T_, 4 * ENH, NI_);

    // 3) zero encoder h/c state
    cudaMemsetAsync(encst, 0, sizeof(float) * 4 * B_ * ENH, 0);

    // 4) encoder recurrence (fwd + bwd per step)
    for (int s = 0; s < T_; s++) {
        gemm_small(hf, ENH, enc_Whh_f, ENH, nullptr,
                   xgf + (size_t)s * 4 * ENH, T_ * 4 * ENH,
                   gf, 4 * ENH, B_, 4 * ENH, ENH);
        gemm_small(hb, ENH, enc_Whh_b, ENH, nullptr,
                   xgb + (size_t)(T_ - 1 - s) * 4 * ENH, T_ * 4 * ENH,
                   gb, 4 * ENH, B_, 4 * ENH, ENH);
        enc_gates<<<(2 * B_ * ENH + EW - 1) / EW, EW>>>(gf, gb, hf, cf, hb, cb);
    }

    // 5) fhs = [hf, hb]
    concat_fhs<<<(B_ * 2 * ENH + EW - 1) / EW, EW>>>(hf, hb, fhs);

    // 6) mu/logvar
    gemm_small(fhs, 2 * ENH, enc_lin, 2 * ENH, nullptr, nullptr, 0,
               muvar, 2 * NZ_, B_, 2 * NZ_, 2 * ENH);

    // 7) kl
    kl_kernel<<<1, B_>>>(muvar, out_kl);

    // 8) root = mu @ z2dec_W^T + b   (mu = muvar[:, :NZ_], lda = 2*NZ_)
    gemm_small(muvar, 2 * NZ_, z2dec_W, NZ_, z2dec_b, nullptr, 0,
               root, DNH, B_, DNH, NZ_);

    // 9) VQ
    vq_kernel<<<B_ * ND_, 256>>>(fhs, codebooks, inds, q, vqp);
    vq_finish<<<1, B_>>>(vqp, inds, out_vq, out_inds);

    // 10) suffix = q_st @ suffix_W^T
    gemm_small(q, ND_ * D_, suffix_W, ND_ * D_, nullptr, nullptr, 0,
               suffix, NI_, B_, NI_, ND_ * D_);

    // 11) decoder embeddings + suffix broadcast
    demb_kernel<<<(B_ * T_ * NI_ + EW - 1) / EW, EW>>>(x, dec_embed, suffix, demb);

    // 12) decoder input gates
    gemm_big(demb, NI_, dec_Wih, NI_, dec_b, nullptr, 0, xgd, 4 * DNH, B_ * T_, 4 * DNH, NI_);

    // 13) decoder init: h0 = tanh(root), c0 = root
    dec_init<<<(B_ * DNH + EW - 1) / EW, EW>>>(root, hd0, cd);

    // 14) decoder recurrence; h written straight into decout slices
    for (int s = 0; s < T_; s++) {
        const float* A   = (s == 0) ? hd0 : (decout + (size_t)(s - 1) * DNH);
        int          lda = (s == 0) ? DNH : (T_ * DNH);
        gemm_small(A, lda, dec_Whh, DNH, nullptr,
                   xgd + (size_t)s * 4 * DNH, T_ * 4 * DNH,
                   gd, 4 * DNH, B_, 4 * DNH, DNH);
        dec_gates<<<(B_ * DNH + EW - 1) / EW, EW>>>(gd, cd, decout + (size_t)s * DNH);
    }

    // 15) logits = decout @ pred_W^T  (N = 10000 guarded)
    gemm_big(decout, DNH, pred_W, DNH, nullptr, nullptr, 0,
             out_log, V_, B_ * T_, V_, DNH);
}

// round 7
// speedup vs baseline: 1.0113x; 1.0093x over previous
#include <cuda_runtime.h>
#include <cuda_bf16.h>
#include <math.h>
#include <stdint.h>

#define B_    128
#define T_    64
#define V_    10000
#define NI_   512
#define ENH   640
#define DNH   1024
#define NZ_   128
#define ND_   8
#define K_    1024
#define D_    160
#define LOGITS_ELEMS (B_ * T_ * V_)

// ---------------- scratch ----------------
__device__ __align__(256) float g_we   [B_ * T_ * NI_];
__device__ __align__(256) float g_xgf  [B_ * T_ * 4 * ENH];
__device__ __align__(256) float g_xgb  [B_ * T_ * 4 * ENH];
__device__ __align__(256) float g_encA [4 * B_ * ENH];   // hfA, cf, hbA, cb
__device__ __align__(256) float g_hfB  [B_ * ENH];
__device__ __align__(256) float g_hbB  [B_ * ENH];
__device__ __align__(256) float g_fhs  [B_ * 2 * ENH];
__device__ __align__(256) float g_muvar[B_ * 2 * NZ_];
__device__ __align__(256) float g_root [B_ * DNH];
__device__ __align__(256) int   g_inds [B_ * ND_];
__device__ __align__(256) float g_q    [B_ * ND_ * D_];
__device__ __align__(256) float g_vqp  [B_ * ND_];
__device__ __align__(256) float g_suffix[B_ * NI_];
__device__ __align__(256) float g_demb [B_ * T_ * NI_];
__device__ __align__(256) float g_xgd  [B_ * T_ * 4 * DNH];
__device__ __align__(256) float g_hd0  [B_ * DNH];
__device__ __align__(256) float g_cd   [B_ * DNH];
__device__ __align__(256) float g_decout[B_ * T_ * DNH];

// ---------------- fp32 SGEMM (encoder path; exact numerics kept) ----------------
template<int BM, int BN, int BK, int TM, int TN>
__global__ __launch_bounds__((BM/TM)*(BN/TN))
void gemm_k(const float* __restrict__ A, int lda,
            const float* __restrict__ W, int ldw,
            const float* __restrict__ bias,
            const float* __restrict__ Cadd, int ldca,
            float* __restrict__ C, int ldc,
            int N, int K)
{
    constexpr int NT = (BM/TM)*(BN/TN);
    __shared__ __align__(16) float As[BK][BM + 4];
    __shared__ __align__(16) float Ws[BK][BN + 4];
    const int tid  = threadIdx.x;
    const int row0 = blockIdx.y * BM;
    const int col0 = blockIdx.x * BN;
    const int tr   = tid / (BN / TN);
    const int tc   = tid % (BN / TN);
    float acc[TM][TN];
#pragma unroll
    for (int i = 0; i < TM; i++)
#pragma unroll
        for (int j = 0; j < TN; j++) acc[i][j] = 0.f;
    for (int k0 = 0; k0 < K; k0 += BK) {
#pragma unroll
        for (int idx = tid * 4; idx < BM * BK; idx += NT * 4) {
            int m = idx / BK, kk = idx % BK;
            float4 v = *reinterpret_cast<const float4*>(A + (size_t)(row0 + m) * lda + (k0 + kk));
            As[kk+0][m]=v.x; As[kk+1][m]=v.y; As[kk+2][m]=v.z; As[kk+3][m]=v.w;
        }
#pragma unroll
        for (int idx = tid * 4; idx < BN * BK; idx += NT * 4) {
            int n = idx / BK, kk = idx % BK;
            float4 v = make_float4(0.f,0.f,0.f,0.f);
            if (col0 + n < N)
                v = *reinterpret_cast<const float4*>(W + (size_t)(col0 + n) * ldw + (k0 + kk));
            Ws[kk+0][n]=v.x; Ws[kk+1][n]=v.y; Ws[kk+2][n]=v.z; Ws[kk+3][n]=v.w;
        }
        __syncthreads();
#pragma unroll
        for (int kk = 0; kk < BK; kk++) {
            float ra[TM], rb[TN];
#pragma unroll
            for (int i = 0; i < TM; i += 4) {
                float4 v = *reinterpret_cast<const float4*>(&As[kk][tr*TM+i]);
                ra[i]=v.x; ra[i+1]=v.y; ra[i+2]=v.z; ra[i+3]=v.w;
            }
#pragma unroll
            for (int j = 0; j < TN; j += 4) {
                float4 v = *reinterpret_cast<const float4*>(&Ws[kk][tc*TN+j]);
                rb[j]=v.x; rb[j+1]=v.y; rb[j+2]=v.z; rb[j+3]=v.w;
            }
#pragma unroll
            for (int i = 0; i < TM; i++)
#pragma unroll
                for (int j = 0; j < TN; j++)
                    acc[i][j] = fmaf(ra[i], rb[j], acc[i][j]);
        }
        __syncthreads();
    }
#pragma unroll
    for (int i = 0; i < TM; i++) {
        int m = row0 + tr*TM + i;
#pragma unroll
        for (int j = 0; j < TN; j++) {
            int n = col0 + tc*TN + j;
            if (n < N) {
                float v = acc[i][j];
                if (bias) v += bias[n];
                if (Cadd) v += Cadd[(size_t)m * ldca + n];
                C[(size_t)m * ldc + n] = v;
            }
        }
    }
}

// ---------------- split-bf16 tensor-core GEMM: C = A @ W^T (+bias) ----------------
// A [M,K] f32 row-major, W [N,K] f32 row-major. M%128==0, K%32==0, N guarded.
#define MMA_BF16(CC, AA, BB)                                                     \
    asm volatile("mma.sync.aligned.m16n8k16.row.col.f32.bf16.bf16.f32 "          \
        "{%0,%1,%2,%3}, {%4,%5,%6,%7}, {%8,%9}, {%0,%1,%2,%3};"                  \
        : "+f"(CC[0]), "+f"(CC[1]), "+f"(CC[2]), "+f"(CC[3])                     \
        : "r"(AA[0]), "r"(AA[1]), "r"(AA[2]), "r"(AA[3]), "r"(BB[0]), "r"(BB[1]))

__global__ __launch_bounds__(256)
void hgemm_split(const float* __restrict__ A, int lda,
                 const float* __restrict__ W, int ldw,
                 const float* __restrict__ bias,
                 float* __restrict__ C, int ldc, int N, int K)
{
    __shared__ __align__(16) __nv_bfloat16 Ah[128][40];
    __shared__ __align__(16) __nv_bfloat16 Al[128][40];
    __shared__ __align__(16) __nv_bfloat16 Wh[128][40];
    __shared__ __align__(16) __nv_bfloat16 Wl[128][40];
    const int tid  = threadIdx.x;
    const int warp = tid >> 5, lane = tid & 31;
    const int wm = warp >> 2, wn = warp & 3;      // 2 x 4 warp grid; warp tile 64x32
    const int row0 = blockIdx.y * 128, col0 = blockIdx.x * 128;
    const int g = lane >> 2, q = lane & 3;

    float acc[4][4][4];
#pragma unroll
    for (int a = 0; a < 4; a++)
#pragma unroll
        for (int b = 0; b < 4; b++)
#pragma unroll
            for (int c = 0; c < 4; c++) acc[a][b][c] = 0.f;

    for (int k0 = 0; k0 < K; k0 += 32) {
        __syncthreads();
        for (int i = tid; i < 128 * 8; i += 256) {
            int r = i >> 3, c4 = (i & 7) << 2;
            float4 va = *reinterpret_cast<const float4*>(&A[(size_t)(row0 + r) * lda + k0 + c4]);
            float xa[4] = {va.x, va.y, va.z, va.w};
#pragma unroll
            for (int e = 0; e < 4; e++) {
                __nv_bfloat16 h = __float2bfloat16_rn(xa[e]);
                Ah[r][c4+e] = h;
                Al[r][c4+e] = __float2bfloat16_rn(xa[e] - __bfloat162float(h));
            }
            float4 vw = make_float4(0.f,0.f,0.f,0.f);
            if (col0 + r < N)
                vw = *reinterpret_cast<const float4*>(&W[(size_t)(col0 + r) * ldw + k0 + c4]);
            float xw[4] = {vw.x, vw.y, vw.z, vw.w};
#pragma unroll
            for (int e = 0; e < 4; e++) {
                __nv_bfloat16 h = __float2bfloat16_rn(xw[e]);
                Wh[r][c4+e] = h;
                Wl[r][c4+e] = __float2bfloat16_rn(xw[e] - __bfloat162float(h));
            }
        }
        __syncthreads();
#pragma unroll
        for (int ks = 0; ks < 32; ks += 16) {
            uint32_t ah[4][4], al[4][4], bh[4][2], bl[4][2];
#pragma unroll
            for (int mi = 0; mi < 4; mi++) {
                int r = wm*64 + mi*16 + g;
                ah[mi][0] = *reinterpret_cast<const uint32_t*>(&Ah[r  ][ks + 2*q    ]);
                ah[mi][1] = *reinterpret_cast<const uint32_t*>(&Ah[r+8][ks + 2*q    ]);
                ah[mi][2] = *reinterpret_cast<const uint32_t*>(&Ah[r  ][ks + 2*q + 8]);
                ah[mi][3] = *reinterpret_cast<const uint32_t*>(&Ah[r+8][ks + 2*q + 8]);
                al[mi][0] = *reinterpret_cast<const uint32_t*>(&Al[r  ][ks + 2*q    ]);
                al[mi][1] = *reinterpret_cast<const uint32_t*>(&Al[r+8][ks + 2*q    ]);
                al[mi][2] = *reinterpret_cast<const uint32_t*>(&Al[r  ][ks + 2*q + 8]);
                al[mi][3] = *reinterpret_cast<const uint32_t*>(&Al[r+8][ks + 2*q + 8]);
            }
#pragma unroll
            for (int ni = 0; ni < 4; ni++) {
                int c = wn*32 + ni*8 + g;
                bh[ni][0] = *reinterpret_cast<const uint32_t*>(&Wh[c][ks + 2*q    ]);
                bh[ni][1] = *reinterpret_cast<const uint32_t*>(&Wh[c][ks + 2*q + 8]);
                bl[ni][0] = *reinterpret_cast<const uint32_t*>(&Wl[c][ks + 2*q    ]);
                bl[ni][1] = *reinterpret_cast<const uint32_t*>(&Wl[c][ks + 2*q + 8]);
            }
#pragma unroll
            for (int mi = 0; mi < 4; mi++)
#pragma unroll
                for (int ni = 0; ni < 4; ni++) {
                    MMA_BF16(acc[mi][ni], ah[mi], bh[ni]);
                    MMA_BF16(acc[mi][ni], ah[mi], bl[ni]);
                    MMA_BF16(acc[mi][ni], al[mi], bh[ni]);
                }
        }
    }
#pragma unroll
    for (int mi = 0; mi < 4; mi++) {
        int r = row0 + wm*64 + mi*16 + g;
#pragma unroll
        for (int ni = 0; ni < 4; ni++) {
            int c = col0 + wn*32 + ni*8 + 2*q;
            float b0 = 0.f, b1 = 0.f;
            if (bias) {
                if (c < N)     b0 = bias[c];
                if (c + 1 < N) b1 = bias[c+1];
            }
            if (c < N) {
                C[(size_t)r * ldc + c]     = acc[mi][ni][0] + b0;
                C[(size_t)(r+8) * ldc + c] = acc[mi][ni][2] + b0;
            }
            if (c + 1 < N) {
                C[(size_t)r * ldc + c + 1]     = acc[mi][ni][1] + b1;
                C[(size_t)(r+8) * ldc + c + 1] = acc[mi][ni][3] + b1;
            }
        }
    }
}

// ---------------- fused LSTM step ----------------
// Block: 256 threads = 8 warps = 4 j-columns x 2 gate-pairs; lane owns 4 batch rows.
// grid.x = H/4 j-blocks; grid.y = 1 (dec) or 2 (enc fwd+bwd).
__device__ __forceinline__ float sigf(float x) { return 1.f / (1.f + expf(-x)); }

template<int H>
__global__ __launch_bounds__(256)
void lstm_step(const float* __restrict__ xg0, const float* __restrict__ xg1, int rsXG,
               const float* __restrict__ W0,  const float* __restrict__ W1,
               const float* __restrict__ h0in, const float* __restrict__ h1in, int rsHin,
               float* __restrict__ c0p, float* __restrict__ c1p,
               float* __restrict__ h0out, float* __restrict__ h1out, int rsHout)
{
    const float* xg;  const float* Whh; const float* hin; float* cp; float* hout;
    if (blockIdx.y == 0) { xg = xg0; Whh = W0; hin = h0in; cp = c0p; hout = h0out; }
    else                 { xg = xg1; Whh = W1; hin = h1in; cp = c1p; hout = h1out; }

    __shared__ __align__(16) float hs[32][132];      // [k][b]
    __shared__ __align__(16) float ws[4][4][32];     // [gate][j][k]
    __shared__ float sg[4][4][128];                  // [gate][j][b]

    const int tid  = threadIdx.x;
    const int lane = tid & 31, w = tid >> 5;
    const int jw = w >> 1, gp = w & 1;               // j within block, gate pair
    const int g0 = 2 * gp, g1 = 2 * gp + 1;
    const int jb0 = blockIdx.x * 4;

    float a0[4] = {0.f,0.f,0.f,0.f};
    float a1[4] = {0.f,0.f,0.f,0.f};

    for (int k0 = 0; k0 < H; k0 += 32) {
        __syncthreads();
        for (int i = tid; i < 128 * 8; i += 256) {
            int b = i >> 3, c4 = (i & 7) << 2;
            float4 v = *reinterpret_cast<const float4*>(&hin[(size_t)b * rsHin + k0 + c4]);
            hs[c4+0][b]=v.x; hs[c4+1][b]=v.y; hs[c4+2][b]=v.z; hs[c4+3][b]=v.w;
        }
        for (int i = tid; i < 4 * 4 * 8; i += 256) {
            int gg = i >> 5, rem = i & 31;
            int jj = rem >> 3, c4 = (rem & 7) << 2;
            float4 v = *reinterpret_cast<const float4*>(
                &Whh[(size_t)(gg * H + jb0 + jj) * H + k0 + c4]);
            ws[gg][jj][c4+0]=v.x; ws[gg][jj][c4+1]=v.y; ws[gg][jj][c4+2]=v.z; ws[gg][jj][c4+3]=v.w;
        }
        __syncthreads();
#pragma unroll
        for (int kk = 0; kk < 32; kk++) {
            float4 hv = *reinterpret_cast<const float4*>(&hs[kk][lane * 4]);
            float w0v = ws[g0][jw][kk], w1v = ws[g1][jw][kk];
            a0[0] = fmaf(hv.x, w0v, a0[0]); a1[0] = fmaf(hv.x, w1v, a1[0]);
            a0[1] = fmaf(hv.y, w0v, a0[1]); a1[1] = fmaf(hv.y, w1v, a1[1]);
            a0[2] = fmaf(hv.z, w0v, a0[2]); a1[2] = fmaf(hv.z, w1v, a1[2]);
            a0[3] = fmaf(hv.w, w0v, a0[3]); a1[3] = fmaf(hv.w, w1v, a1[3]);
        }
    }
#pragma unroll
    for (int e = 0; e < 4; e++) {
        sg[g0][jw][lane*4 + e] = a0[e];
        sg[g1][jw][lane*4 + e] = a1[e];
    }
    __syncthreads();
    for (int p = tid; p < 4 * 128; p += 256) {
        int j = p >> 7, b = p & 127;
        int jg = jb0 + j;
        const float* xr = xg + (size_t)b * rsXG;
        float gi = sg[0][j][b] + xr[0*H + jg];
        float gf = sg[1][j][b] + xr[1*H + jg];
        float gc = sg[2][j][b] + xr[2*H + jg];
        float go = sg[3][j][b] + xr[3*H + jg];
        size_t ci = (size_t)b * H + jg;
        float cc = sigf(gf) * cp[ci] + sigf(gi) * tanhf(gc);
        cp[ci] = cc;
        hout[(size_t)b * rsHout + jg] = sigf(go) * tanhf(cc);
    }
}

// ---------------- elementwise / small kernels ----------------
__global__ void embed_kernel(const int* __restrict__ x, const float* __restrict__ emb,
                             float* __restrict__ out)
{
    size_t idx = (size_t)blockIdx.x * blockDim.x + threadIdx.x;
    if (idx >= (size_t)B_ * T_ * NI_) return;
    int i = (int)(idx % NI_), bt = (int)(idx / NI_);
    out[idx] = emb[(size_t)x[bt] * NI_ + i];
}

__global__ void demb_kernel(const int* __restrict__ x, const float* __restrict__ emb,
                            const float* __restrict__ suffix, float* __restrict__ out)
{
    size_t idx = (size_t)blockIdx.x * blockDim.x + threadIdx.x;
    if (idx >= (size_t)B_ * T_ * NI_) return;
    int i = (int)(idx % NI_), bt = (int)(idx / NI_);
    int b = bt / T_;
    out[idx] = emb[(size_t)x[bt] * NI_ + i] + suffix[(size_t)b * NI_ + i];
}

__global__ void concat_fhs(const float* __restrict__ hf, const float* __restrict__ hb,
                           float* __restrict__ fhs)
{
    int idx = blockIdx.x * blockDim.x + threadIdx.x;
    if (idx >= B_ * 2 * ENH) return;
    int b = idx / (2 * ENH), j = idx % (2 * ENH);
    fhs[idx] = (j < ENH) ? hf[(size_t)b * ENH + j] : hb[(size_t)b * ENH + (j - ENH)];
}

__global__ void kl_kernel(const float* __restrict__ muvar, float* __restrict__ out_kl)
{
    int b = threadIdx.x;
    if (b >= B_) return;
    float s = 0.f;
    const float* row = muvar + (size_t)b * 2 * NZ_;
    for (int j = 0; j < NZ_; j++) {
        float mu = row[j], lv = row[NZ_ + j];
        s += mu * mu + expf(lv) - lv - 1.f;
    }
    out_kl[b] = 0.5f * s;
}

__global__ void dec_init(const float* __restrict__ root, float* __restrict__ h0,
                         float* __restrict__ c0)
{
    int idx = blockIdx.x * blockDim.x + threadIdx.x;
    if (idx >= B_ * DNH) return;
    float r = root[idx];
    h0[idx] = tanhf(r);
    c0[idx] = r;
}

__global__ void vq_kernel(const float* __restrict__ fhs, const float* __restrict__ cb,
                          int* __restrict__ inds, float* __restrict__ q,
                          float* __restrict__ vqp)
{
    const int bn = blockIdx.x;
    const int b = bn / ND_, n = bn % ND_;
    __shared__ __align__(16) float lat[D_];
    __shared__ float svals[256];
    __shared__ int   sidx[256];
    const float* latg = fhs + (size_t)b * (ND_ * D_) + (size_t)n * D_;
    for (int d = threadIdx.x; d < D_; d += 256) lat[d] = latg[d];
    __syncthreads();
    float best = INFINITY; int bidx = K_;
    const float* cbn = cb + (size_t)n * K_ * D_;
    for (int k = threadIdx.x; k < K_; k += 256) {
        const float4* ck = reinterpret_cast<const float4*>(cbn + (size_t)k * D_);
        float t1 = 0.f, t2 = 0.f;
#pragma unroll
        for (int d4 = 0; d4 < D_ / 4; d4++) {
            float4 cv = ck[d4];
            const float4 lv = *reinterpret_cast<const float4*>(&lat[d4 * 4]);
            t1 = fmaf(cv.x, cv.x, t1); t2 = fmaf(cv.x, lv.x, t2);
            t1 = fmaf(cv.y, cv.y, t1); t2 = fmaf(cv.y, lv.y, t2);
            t1 = fmaf(cv.z, cv.z, t1); t2 = fmaf(cv.z, lv.z, t2);
            t1 = fmaf(cv.w, cv.w, t1); t2 = fmaf(cv.w, lv.w, t2);
        }
        float dist = t1 - 2.f * t2;
        if (dist < best || (dist == best && k < bidx)) { best = dist; bidx = k; }
    }
    svals[threadIdx.x] = best; sidx[threadIdx.x] = bidx;
    __syncthreads();
    for (int off = 128; off > 0; off >>= 1) {
        if (threadIdx.x < off) {
            float v = svals[threadIdx.x + off]; int i2 = sidx[threadIdx.x + off];
            if (v < svals[threadIdx.x] || (v == svals[threadIdx.x] && i2 < sidx[threadIdx.x])) {
                svals[threadIdx.x] = v; sidx[threadIdx.x] = i2;
            }
        }
        __syncthreads();
    }
    const int kmin = sidx[0];
    if (threadIdx.x == 0) inds[bn] = kmin;
    __syncthreads();
    const float* ck = cbn + (size_t)kmin * D_;
    float part = 0.f;
    for (int d = threadIdx.x; d < D_; d += 256) {
        float qv = ck[d], lv = lat[d];
        float diff = qv - lv;
        q[(size_t)bn * D_ + d] = lv + diff;
        part += diff * diff;
    }
    svals[threadIdx.x] = part;
    __syncthreads();
    for (int off = 128; off > 0; off >>= 1) {
        if (threadIdx.x < off) svals[threadIdx.x] += svals[threadIdx.x + off];
        __syncthreads();
    }
    if (threadIdx.x == 0) vqp[bn] = svals[0] / (float)D_;
}

__global__ void vq_finish(const float* __restrict__ vqp, const int* __restrict__ inds,
                          float* __restrict__ out_vq, float* __restrict__ out_inds)
{
    int b = threadIdx.x;
    if (b >= B_) return;
    float s = 0.f;
#pragma unroll
    for (int n = 0; n < ND_; n++) s += vqp[b * ND_ + n];
    out_vq[b] = 1.25f * s;
#pragma unroll
    for (int n = 0; n < ND_; n++)
        out_inds[b * ND_ + n] = (float)inds[b * ND_ + n];
}

// ---------------- launch helpers ----------------
static inline void gemm_big(const float* A, int lda, const float* W, int ldw,
                            const float* bias, float* C, int ldc, int M, int N, int K)
{
    dim3 grid((N + 127) / 128, M / 128);
    gemm_k<128, 128, 16, 8, 8><<<grid, 256>>>(A, lda, W, ldw, bias, nullptr, 0, C, ldc, N, K);
}
static inline void gemm_small(const float* A, int lda, const float* W, int ldw,
                              const float* bias, float* C, int ldc, int M, int N, int K)
{
    dim3 grid((N + 63) / 64, M / 32);
    gemm_k<32, 64, 16, 4, 4><<<grid, 128>>>(A, lda, W, ldw, bias, nullptr, 0, C, ldc, N, K);
}
static inline void gemm_tc(const float* A, int lda, const float* W, int ldw,
                           const float* bias, float* C, int ldc, int M, int N, int K)
{
    dim3 grid((N + 127) / 128, M / 128);
    hgemm_split<<<grid, 256>>>(A, lda, W, ldw, bias, C, ldc, N, K);
}

extern "C" void kernel_launch(void* const* d_in, const int* in_sizes, int n_in,
                              void* d_out, int out_size)
{
    (void)in_sizes; (void)n_in; (void)out_size;
    const int*   x         = (const int*)  d_in[0];
    const float* enc_embed = (const float*)d_in[1];
    const float* enc_Wih_f = (const float*)d_in[2];
    const float* enc_Whh_f = (const float*)d_in[3];
    const float* enc_b_f   = (const float*)d_in[4];
    const float* enc_Wih_b = (const float*)d_in[5];
    const float* enc_Whh_b = (const float*)d_in[6];
    const float* enc_b_b   = (const float*)d_in[7];
    const float* enc_lin   = (const float*)d_in[8];
    const float* z2dec_W   = (const float*)d_in[9];
    const float* z2dec_b   = (const float*)d_in[10];
    const float* codebooks = (const float*)d_in[11];
    const float* suffix_W  = (const float*)d_in[12];
    const float* dec_embed = (const float*)d_in[13];
    const float* dec_Wih   = (const float*)d_in[14];
    const float* dec_Whh   = (const float*)d_in[15];
    const float* dec_b     = (const float*)d_in[16];
    const float* pred_W    = (const float*)d_in[17];

    float* out      = (float*)d_out;
    float* out_log  = out;
    float* out_vq   = out + (size_t)LOGITS_ELEMS;
    float* out_kl   = out_vq + B_;
    float* out_inds = out_kl + B_;

    float *we,*xgf,*xgb,*encA,*hfB,*hbB,*fhs,*muvar,*root,*q,*vqp,*suffix;
    float *demb,*xgd,*hd0,*cd,*decout;
    int* inds;
    cudaGetSymbolAddress((void**)&we,    g_we);
    cudaGetSymbolAddress((void**)&xgf,   g_xgf);
    cudaGetSymbolAddress((void**)&xgb,   g_xgb);
    cudaGetSymbolAddress((void**)&encA,  g_encA);
    cudaGetSymbolAddress((void**)&hfB,   g_hfB);
    cudaGetSymbolAddress((void**)&hbB,   g_hbB);
    cudaGetSymbolAddress((void**)&fhs,   g_fhs);
    cudaGetSymbolAddress((void**)&muvar, g_muvar);
    cudaGetSymbolAddress((void**)&root,  g_root);
    cudaGetSymbolAddress((void**)&inds,  g_inds);
    cudaGetSymbolAddress((void**)&q,     g_q);
    cudaGetSymbolAddress((void**)&vqp,   g_vqp);
    cudaGetSymbolAddress((void**)&suffix,g_suffix);
    cudaGetSymbolAddress((void**)&demb,  g_demb);
    cudaGetSymbolAddress((void**)&xgd,   g_xgd);
    cudaGetSymbolAddress((void**)&hd0,   g_hd0);
    cudaGetSymbolAddress((void**)&cd,    g_cd);
    cudaGetSymbolAddress((void**)&decout,g_decout);

    float* hfA = encA;
    float* cf  = encA + (size_t)B_ * ENH;
    float* hbA = encA + (size_t)2 * B_ * ENH;
    float* cb  = encA + (size_t)3 * B_ * ENH;

    const int EW = 256;

    // encoder embedding + input-gate GEMMs (fp32 exact)
    embed_kernel<<<(B_ * T_ * NI_ + EW - 1) / EW, EW>>>(x, enc_embed, we);
    gemm_big(we, NI_, enc_Wih_f, NI_, enc_b_f, xgf, 4 * ENH, B_ * T_, 4 * ENH, NI_);
    gemm_big(we, NI_, enc_Wih_b, NI_, enc_b_b, xgb, 4 * ENH, B_ * T_, 4 * ENH, NI_);
    cudaMemsetAsync(encA, 0, sizeof(float) * 4 * B_ * ENH, 0);

    // encoder recurrence: fwd + bwd fused, h double-buffered
    {
        dim3 grid(ENH / 4, 2);
        for (int s = 0; s < T_; s++) {
            const float* hf_in = (s & 1) ? hfB : hfA;
            float*       hf_out= (s & 1) ? hfA : hfB;
            const float* hb_in = (s & 1) ? hbB : hbA;
            float*       hb_out= (s & 1) ? hbA : hbB;
            lstm_step<ENH><<<grid, 256>>>(
                xgf + (size_t)s * 4 * ENH, xgb + (size_t)(T_ - 1 - s) * 4 * ENH, T_ * 4 * ENH,
                enc_Whh_f, enc_Whh_b,
                hf_in, hb_in, ENH,
                cf, cb,
                hf_out, hb_out, ENH);
        }
    }
    // after 64 steps (even count), final h is in the A buffers
    concat_fhs<<<(B_ * 2 * ENH + EW - 1) / EW, EW>>>(hfA, hbA, fhs);

    gemm_small(fhs, 2 * ENH, enc_lin, 2 * ENH, nullptr, muvar, 2 * NZ_, B_, 2 * NZ_, 2 * ENH);
    kl_kernel<<<1, B_>>>(muvar, out_kl);
    gemm_small(muvar, 2 * NZ_, z2dec_W, NZ_, z2dec_b, root, DNH, B_, DNH, NZ_);

    vq_kernel<<<B_ * ND_, 256>>>(fhs, codebooks, inds, q, vqp);
    vq_finish<<<1, B_>>>(vqp, inds, out_vq, out_inds);

    gemm_small(q, ND_ * D_, suffix_W, ND_ * D_, nullptr, suffix, NI_, B_, NI_, ND_ * D_);
    demb_kernel<<<(B_ * T_ * NI_ + EW - 1) / EW, EW>>>(x, dec_embed, suffix, demb);

    // decoder input gates: tensor-core split-bf16
    gemm_tc(demb, NI_, dec_Wih, NI_, dec_b, xgd, 4 * DNH, B_ * T_, 4 * DNH, NI_);

    dec_init<<<(B_ * DNH + EW - 1) / EW, EW>>>(root, hd0, cd);

    // decoder recurrence: fused step, h written straight into decout slices
    {
        dim3 grid(DNH / 4, 1);
        for (int s = 0; s < T_; s++) {
            const float* hin = (s == 0) ? hd0 : (decout + (size_t)(s - 1) * DNH);
            int rsHin        = (s == 0) ? DNH : (T_ * DNH);
            const float* xgs = xgd + (size_t)s * 4 * DNH;
            lstm_step<DNH><<<grid, 256>>>(
                xgs, xgs, T_ * 4 * DNH,
                dec_Whh, dec_Whh,
                hin, hin, rsHin,
                cd, cd,
                decout + (size_t)s * DNH, decout + (size_t)s * DNH, T_ * DNH);
        }
    }

    // logits: tensor-core split-bf16
    gemm_tc(decout, DNH, pred_W, DNH, nullptr, out_log, V_, B_ * T_, V_, DNH);
}